// round 1
// baseline (speedup 1.0000x reference)
#include <cuda_runtime.h>

// Problem constants
#define BATCH 32
#define CH    2048
#define NHW   576      // 24*24
#define MID   256

// GEMM tiling
#define BM 64
#define BN 64
#define BK 16
#define TM 4
#define TN 4
#define NT 256

// Scratch (device globals: allowed; no allocation)
__device__ float g_f1[(size_t)BATCH * MID * NHW];
__device__ float g_f2[(size_t)BATCH * MID * NHW];
__device__ float g_attn[(size_t)BATCH * NHW * NHW];

// ---------------------------------------------------------------------------
// Kernel 1: f1 = W1 @ feat, f2 = W2 @ feat  (per batch), sharing the feat tile.
// f[m][n] = sum_c W[m][c] * feat[c][n].  grid (NHW/BN, MID/BM, BATCH)
// ---------------------------------------------------------------------------
__global__ __launch_bounds__(NT) void k_conv(const float* __restrict__ feat,
                                             const float* __restrict__ W1,
                                             const float* __restrict__ W2) {
    __shared__ float As1[BK][BM + 4];
    __shared__ float As2[BK][BM + 4];
    __shared__ float Bs[BK][BN];

    const int b  = blockIdx.z;
    const int m0 = blockIdx.y * BM;
    const int n0 = blockIdx.x * BN;
    const float* fb = feat + (size_t)b * CH * NHW;

    const int tid = threadIdx.x;
    const int tx = tid & 15, ty = tid >> 4;
    const int lr = tid >> 2;            // 0..63 : m-row within tile
    const int lq = (tid & 3) << 2;      // 0,4,8,12 : k offset
    const int bk = tid >> 4;            // 0..15 : k row for B tile
    const int bn = (tid & 15) << 2;     // 0..60 : n offset

    float acc1[TM][TN] = {};
    float acc2[TM][TN] = {};

    for (int k0 = 0; k0 < CH; k0 += BK) {
        float4 a1 = *(const float4*)(W1 + (size_t)(m0 + lr) * CH + k0 + lq);
        float4 a2 = *(const float4*)(W2 + (size_t)(m0 + lr) * CH + k0 + lq);
        As1[lq + 0][lr] = a1.x; As1[lq + 1][lr] = a1.y;
        As1[lq + 2][lr] = a1.z; As1[lq + 3][lr] = a1.w;
        As2[lq + 0][lr] = a2.x; As2[lq + 1][lr] = a2.y;
        As2[lq + 2][lr] = a2.z; As2[lq + 3][lr] = a2.w;
        *(float4*)&Bs[bk][bn] =
            *(const float4*)(fb + (size_t)(k0 + bk) * NHW + n0 + bn);
        __syncthreads();

        #pragma unroll
        for (int k = 0; k < BK; ++k) {
            float bv[TN], a1v[TM], a2v[TM];
            #pragma unroll
            for (int j = 0; j < TN; ++j) bv[j] = Bs[k][tx * TN + j];
            #pragma unroll
            for (int i = 0; i < TM; ++i) {
                a1v[i] = As1[k][ty * TM + i];
                a2v[i] = As2[k][ty * TM + i];
            }
            #pragma unroll
            for (int i = 0; i < TM; ++i)
                #pragma unroll
                for (int j = 0; j < TN; ++j) {
                    acc1[i][j] += a1v[i] * bv[j];
                    acc2[i][j] += a2v[i] * bv[j];
                }
        }
        __syncthreads();
    }

    const size_t base = (size_t)b * MID * NHW;
    #pragma unroll
    for (int i = 0; i < TM; ++i) {
        size_t off = base + (size_t)(m0 + ty * TM + i) * NHW + n0 + tx * TN;
        *(float4*)(g_f1 + off) = make_float4(acc1[i][0], acc1[i][1], acc1[i][2], acc1[i][3]);
        *(float4*)(g_f2 + off) = make_float4(acc2[i][0], acc2[i][1], acc2[i][2], acc2[i][3]);
    }
}

// ---------------------------------------------------------------------------
// Kernel 2: logits[i][j] = sum_m f1[m][i] * f2[m][j]  (per batch)
// grid (NHW/BN, NHW/BM, BATCH), K = MID
// ---------------------------------------------------------------------------
__global__ __launch_bounds__(NT) void k_logits() {
    __shared__ float As[BK][BM];
    __shared__ float Bs[BK][BN];

    const int b  = blockIdx.z;
    const int i0 = blockIdx.y * BM;
    const int j0 = blockIdx.x * BN;
    const float* f1b = g_f1 + (size_t)b * MID * NHW;
    const float* f2b = g_f2 + (size_t)b * MID * NHW;

    const int tid = threadIdx.x;
    const int tx = tid & 15, ty = tid >> 4;
    const int lk = tid >> 4;            // 0..15
    const int lc = (tid & 15) << 2;     // 0..60

    float acc[TM][TN] = {};

    for (int k0 = 0; k0 < MID; k0 += BK) {
        *(float4*)&As[lk][lc] =
            *(const float4*)(f1b + (size_t)(k0 + lk) * NHW + i0 + lc);
        *(float4*)&Bs[lk][lc] =
            *(const float4*)(f2b + (size_t)(k0 + lk) * NHW + j0 + lc);
        __syncthreads();

        #pragma unroll
        for (int k = 0; k < BK; ++k) {
            float av[TM], bv[TN];
            #pragma unroll
            for (int i = 0; i < TM; ++i) av[i] = As[k][ty * TM + i];
            #pragma unroll
            for (int j = 0; j < TN; ++j) bv[j] = Bs[k][tx * TN + j];
            #pragma unroll
            for (int i = 0; i < TM; ++i)
                #pragma unroll
                for (int j = 0; j < TN; ++j) acc[i][j] += av[i] * bv[j];
        }
        __syncthreads();
    }

    float* ab = g_attn + (size_t)b * NHW * NHW;
    #pragma unroll
    for (int i = 0; i < TM; ++i) {
        size_t off = (size_t)(i0 + ty * TM + i) * NHW + j0 + tx * TN;
        *(float4*)(ab + off) = make_float4(acc[i][0], acc[i][1], acc[i][2], acc[i][3]);
    }
}

// ---------------------------------------------------------------------------
// Kernel 3: row softmax over j (576 elems) for each of BATCH*NHW rows.
// One block (256 threads) per row.
// ---------------------------------------------------------------------------
__global__ __launch_bounds__(256) void k_softmax() {
    const size_t row = blockIdx.x;
    float* p = g_attn + row * NHW;
    const int tid = threadIdx.x;

    float v[3];
    int cnt = 0;
    float m = -1e30f;
    for (int i = tid; i < NHW; i += 256) {
        v[cnt] = p[i];
        m = fmaxf(m, v[cnt]);
        ++cnt;
    }
    #pragma unroll
    for (int o = 16; o > 0; o >>= 1) m = fmaxf(m, __shfl_xor_sync(0xffffffffu, m, o));
    __shared__ float redm[8];
    __shared__ float reds[8];
    if ((tid & 31) == 0) redm[tid >> 5] = m;
    __syncthreads();
    m = fmaxf(fmaxf(fmaxf(redm[0], redm[1]), fmaxf(redm[2], redm[3])),
              fmaxf(fmaxf(redm[4], redm[5]), fmaxf(redm[6], redm[7])));

    float s = 0.f;
    for (int c = 0; c < cnt; ++c) { v[c] = __expf(v[c] - m); s += v[c]; }
    #pragma unroll
    for (int o = 16; o > 0; o >>= 1) s += __shfl_xor_sync(0xffffffffu, s, o);
    if ((tid & 31) == 0) reds[tid >> 5] = s;
    __syncthreads();
    s = reds[0] + reds[1] + reds[2] + reds[3] + reds[4] + reds[5] + reds[6] + reds[7];

    const float inv = 1.0f / s;
    cnt = 0;
    for (int i = tid; i < NHW; i += 256) p[i] = v[cnt++] * inv;
}

// ---------------------------------------------------------------------------
// Kernel 4: out[c][n] = cam[c][n] + alpha * sum_j cam[c][j] * attn[n][j]
// grid (NHW/BN, CH/BM, BATCH), K = NHW
// ---------------------------------------------------------------------------
__global__ __launch_bounds__(NT) void k_out(const float* __restrict__ cam,
                                            const float* __restrict__ alpha_p,
                                            float* __restrict__ out) {
    __shared__ float As[BK][BM + 4];
    __shared__ float Bs[BK][BN + 4];

    const int b  = blockIdx.z;
    const int c0 = blockIdx.y * BM;
    const int n0 = blockIdx.x * BN;
    const float* camb = cam + (size_t)b * CH * NHW;
    const float* ab   = g_attn + (size_t)b * NHW * NHW;

    const int tid = threadIdx.x;
    const int tx = tid & 15, ty = tid >> 4;
    const int lr = tid >> 2;            // 0..63
    const int lq = (tid & 3) << 2;      // 0,4,8,12

    float acc[TM][TN] = {};

    for (int k0 = 0; k0 < NHW; k0 += BK) {
        float4 av = *(const float4*)(camb + (size_t)(c0 + lr) * NHW + k0 + lq);
        As[lq + 0][lr] = av.x; As[lq + 1][lr] = av.y;
        As[lq + 2][lr] = av.z; As[lq + 3][lr] = av.w;
        float4 bv = *(const float4*)(ab + (size_t)(n0 + lr) * NHW + k0 + lq);
        Bs[lq + 0][lr] = bv.x; Bs[lq + 1][lr] = bv.y;
        Bs[lq + 2][lr] = bv.z; Bs[lq + 3][lr] = bv.w;
        __syncthreads();

        #pragma unroll
        for (int k = 0; k < BK; ++k) {
            float av2[TM], bv2[TN];
            #pragma unroll
            for (int i = 0; i < TM; ++i) av2[i] = As[k][ty * TM + i];
            #pragma unroll
            for (int j = 0; j < TN; ++j) bv2[j] = Bs[k][tx * TN + j];
            #pragma unroll
            for (int i = 0; i < TM; ++i)
                #pragma unroll
                for (int j = 0; j < TN; ++j) acc[i][j] += av2[i] * bv2[j];
        }
        __syncthreads();
    }

    const float alpha = *alpha_p;
    float* ob = out + (size_t)b * CH * NHW;
    #pragma unroll
    for (int i = 0; i < TM; ++i) {
        size_t off = (size_t)(c0 + ty * TM + i) * NHW + n0 + tx * TN;
        float4 cv = *(const float4*)(camb + off);
        float4 ov;
        ov.x = cv.x + alpha * acc[i][0];
        ov.y = cv.y + alpha * acc[i][1];
        ov.z = cv.z + alpha * acc[i][2];
        ov.w = cv.w + alpha * acc[i][3];
        *(float4*)(ob + off) = ov;
    }
}

// ---------------------------------------------------------------------------
// Inputs (metadata order): cam, feat, W1, W2, alpha. Output: float32 [32,2048,24,24]
// ---------------------------------------------------------------------------
extern "C" void kernel_launch(void* const* d_in, const int* in_sizes, int n_in,
                              void* d_out, int out_size) {
    const float* cam   = (const float*)d_in[0];
    const float* feat  = (const float*)d_in[1];
    const float* W1    = (const float*)d_in[2];
    const float* W2    = (const float*)d_in[3];
    const float* alpha = (const float*)d_in[4];
    float* out = (float*)d_out;

    k_conv<<<dim3(NHW / BN, MID / BM, BATCH), NT>>>(feat, W1, W2);
    k_logits<<<dim3(NHW / BN, NHW / BM, BATCH), NT>>>();
    k_softmax<<<BATCH * NHW, 256>>>();
    k_out<<<dim3(NHW / BN, CH / BM, BATCH), NT>>>(cam, alpha, out);
}

// round 2
// speedup vs baseline: 1.1519x; 1.1519x over previous
#include <cuda_runtime.h>

#define BATCH 32
#define CH    2048
#define NHW   576
#define MID   256
#define BK    16

typedef unsigned long long u64;

__device__ float g_f1[(size_t)BATCH * MID * NHW];
__device__ float g_f2[(size_t)BATCH * MID * NHW];
__device__ float g_attn[(size_t)BATCH * NHW * NHW];

// ---- packed f32x2 helpers (Blackwell FFMA2 path) ----
__device__ __forceinline__ void ffma2(u64& c, u64 a, u64 b) {
    asm("fma.rn.f32x2 %0, %1, %2, %3;" : "=l"(c) : "l"(a), "l"(b), "l"(c));
}
__device__ __forceinline__ u64 pack2(float x, float y) {
    u64 r; asm("mov.b64 %0, {%1, %2};" : "=l"(r) : "f"(x), "f"(y)); return r;
}
__device__ __forceinline__ float2 unpack2(u64 v) {
    float2 r; asm("mov.b64 {%0, %1}, %2;" : "=f"(r.x), "=f"(r.y) : "l"(v)); return r;
}

// ---------------------------------------------------------------------------
// k_conv: f1 = W1@feat, f2 = W2@feat per batch.
// BM=128 (over MID), BN=64, TM=8, TN=4, 256 threads, dual accumulators.
// W is K-fast (transpose on smem store); feat is K-slow (direct).
// ---------------------------------------------------------------------------
__global__ __launch_bounds__(256) void k_conv(const float* __restrict__ feat,
                                              const float* __restrict__ W1,
                                              const float* __restrict__ W2) {
    __shared__ float As1[BK][128 + 4];
    __shared__ float As2[BK][128 + 4];
    __shared__ float Bs[BK][64];

    const int b  = blockIdx.z;
    const int m0 = blockIdx.y * 128;
    const int n0 = blockIdx.x * 64;
    const float* fb = feat + (size_t)b * CH * NHW;

    const int tid = threadIdx.x;
    const int ar = tid >> 2;          // 0..63
    const int ak = (tid & 3) << 2;    // 0,4,8,12
    const int bkr = tid >> 4;         // 0..15
    const int bn = (tid & 15) << 2;   // 0..60
    const int tx = tid & 15;          // 16 * TN(4) = 64
    const int ty = tid >> 4;          // 16 * TM(8) = 128

    u64 acc1[4][4] = {};
    u64 acc2[4][4] = {};

    for (int k0 = 0; k0 < CH; k0 += BK) {
        #pragma unroll
        for (int r = 0; r < 2; ++r) {
            float4 a1 = *(const float4*)(W1 + (size_t)(m0 + ar + 64 * r) * CH + k0 + ak);
            float4 a2 = *(const float4*)(W2 + (size_t)(m0 + ar + 64 * r) * CH + k0 + ak);
            As1[ak + 0][ar + 64 * r] = a1.x; As1[ak + 1][ar + 64 * r] = a1.y;
            As1[ak + 2][ar + 64 * r] = a1.z; As1[ak + 3][ar + 64 * r] = a1.w;
            As2[ak + 0][ar + 64 * r] = a2.x; As2[ak + 1][ar + 64 * r] = a2.y;
            As2[ak + 2][ar + 64 * r] = a2.z; As2[ak + 3][ar + 64 * r] = a2.w;
        }
        *(float4*)&Bs[bkr][bn] = *(const float4*)(fb + (size_t)(k0 + bkr) * NHW + n0 + bn);
        __syncthreads();

        #pragma unroll
        for (int k = 0; k < BK; ++k) {
            const ulonglong2* a1p = (const ulonglong2*)&As1[k][ty * 8];
            const ulonglong2* a2p = (const ulonglong2*)&As2[k][ty * 8];
            ulonglong2 a1lo = a1p[0], a1hi = a1p[1];
            ulonglong2 a2lo = a2p[0], a2hi = a2p[1];
            u64 a1v[4] = {a1lo.x, a1lo.y, a1hi.x, a1hi.y};
            u64 a2v[4] = {a2lo.x, a2lo.y, a2hi.x, a2hi.y};
            float4 bf = *(const float4*)&Bs[k][tx * 4];
            u64 bb[4] = {pack2(bf.x, bf.x), pack2(bf.y, bf.y),
                         pack2(bf.z, bf.z), pack2(bf.w, bf.w)};
            #pragma unroll
            for (int p = 0; p < 4; ++p)
                #pragma unroll
                for (int j = 0; j < 4; ++j) {
                    ffma2(acc1[p][j], a1v[p], bb[j]);
                    ffma2(acc2[p][j], a2v[p], bb[j]);
                }
        }
        __syncthreads();
    }

    const size_t base = (size_t)b * MID * NHW;
    #pragma unroll
    for (int p = 0; p < 4; ++p) {
        const int row0 = m0 + ty * 8 + 2 * p;
        float2 c10 = unpack2(acc1[p][0]), c11 = unpack2(acc1[p][1]);
        float2 c12 = unpack2(acc1[p][2]), c13 = unpack2(acc1[p][3]);
        float2 c20 = unpack2(acc2[p][0]), c21 = unpack2(acc2[p][1]);
        float2 c22 = unpack2(acc2[p][2]), c23 = unpack2(acc2[p][3]);
        size_t o0 = base + (size_t)row0 * NHW + n0 + tx * 4;
        size_t o1 = o0 + NHW;
        *(float4*)(g_f1 + o0) = make_float4(c10.x, c11.x, c12.x, c13.x);
        *(float4*)(g_f1 + o1) = make_float4(c10.y, c11.y, c12.y, c13.y);
        *(float4*)(g_f2 + o0) = make_float4(c20.x, c21.x, c22.x, c23.x);
        *(float4*)(g_f2 + o1) = make_float4(c20.y, c21.y, c22.y, c23.y);
    }
}

// ---------------------------------------------------------------------------
// k_logits: logits[i][j] = sum_m f1[m][i]*f2[m][j]. K=256, both operands K-slow.
// BM=BN=64, TM=TN=8, 64 threads.
// ---------------------------------------------------------------------------
__global__ __launch_bounds__(64) void k_logits() {
    __shared__ float As[BK][64];
    __shared__ float Bs[BK][64];

    const int b  = blockIdx.z;
    const int i0 = blockIdx.y * 64;
    const int j0 = blockIdx.x * 64;
    const float* f1b = g_f1 + (size_t)b * MID * NHW;
    const float* f2b = g_f2 + (size_t)b * MID * NHW;

    const int tid = threadIdx.x;
    const int lc = (tid & 15) << 2;   // 0..60
    const int lk = tid >> 4;          // 0..3 (+4r)
    const int tx = tid & 7;
    const int ty = tid >> 3;

    u64 acc[4][8] = {};

    for (int k0 = 0; k0 < MID; k0 += BK) {
        #pragma unroll
        for (int r = 0; r < 4; ++r) {
            int kr = lk + 4 * r;
            *(float4*)&As[kr][lc] = *(const float4*)(f1b + (size_t)(k0 + kr) * NHW + i0 + lc);
            *(float4*)&Bs[kr][lc] = *(const float4*)(f2b + (size_t)(k0 + kr) * NHW + j0 + lc);
        }
        __syncthreads();

        #pragma unroll
        for (int k = 0; k < BK; ++k) {
            const ulonglong2* ap = (const ulonglong2*)&As[k][ty * 8];
            ulonglong2 alo = ap[0], ahi = ap[1];
            u64 av[4] = {alo.x, alo.y, ahi.x, ahi.y};
            float4 b0 = *(const float4*)&Bs[k][tx * 8];
            float4 b1 = *(const float4*)&Bs[k][tx * 8 + 4];
            u64 bb[8] = {pack2(b0.x, b0.x), pack2(b0.y, b0.y), pack2(b0.z, b0.z), pack2(b0.w, b0.w),
                         pack2(b1.x, b1.x), pack2(b1.y, b1.y), pack2(b1.z, b1.z), pack2(b1.w, b1.w)};
            #pragma unroll
            for (int p = 0; p < 4; ++p)
                #pragma unroll
                for (int j = 0; j < 8; ++j) ffma2(acc[p][j], av[p], bb[j]);
        }
        __syncthreads();
    }

    float* ab = g_attn + (size_t)b * NHW * NHW;
    #pragma unroll
    for (int p = 0; p < 4; ++p) {
        const int row0 = i0 + ty * 8 + 2 * p;
        float2 c[8];
        #pragma unroll
        for (int j = 0; j < 8; ++j) c[j] = unpack2(acc[p][j]);
        size_t o0 = (size_t)row0 * NHW + j0 + tx * 8;
        size_t o1 = o0 + NHW;
        *(float4*)(ab + o0)     = make_float4(c[0].x, c[1].x, c[2].x, c[3].x);
        *(float4*)(ab + o0 + 4) = make_float4(c[4].x, c[5].x, c[6].x, c[7].x);
        *(float4*)(ab + o1)     = make_float4(c[0].y, c[1].y, c[2].y, c[3].y);
        *(float4*)(ab + o1 + 4) = make_float4(c[4].y, c[5].y, c[6].y, c[7].y);
    }
}

// ---------------------------------------------------------------------------
// k_softmax: row softmax over 576 elems, one 256-thread block per row.
// ---------------------------------------------------------------------------
__global__ __launch_bounds__(256) void k_softmax() {
    const size_t row = blockIdx.x;
    float* p = g_attn + row * NHW;
    const int tid = threadIdx.x;

    float v[3];
    int cnt = 0;
    float m = -1e30f;
    for (int i = tid; i < NHW; i += 256) { v[cnt] = p[i]; m = fmaxf(m, v[cnt]); ++cnt; }
    #pragma unroll
    for (int o = 16; o > 0; o >>= 1) m = fmaxf(m, __shfl_xor_sync(0xffffffffu, m, o));
    __shared__ float redm[8], reds[8];
    if ((tid & 31) == 0) redm[tid >> 5] = m;
    __syncthreads();
    m = fmaxf(fmaxf(fmaxf(redm[0], redm[1]), fmaxf(redm[2], redm[3])),
              fmaxf(fmaxf(redm[4], redm[5]), fmaxf(redm[6], redm[7])));

    float s = 0.f;
    for (int c = 0; c < cnt; ++c) { v[c] = __expf(v[c] - m); s += v[c]; }
    #pragma unroll
    for (int o = 16; o > 0; o >>= 1) s += __shfl_xor_sync(0xffffffffu, s, o);
    if ((tid & 31) == 0) reds[tid >> 5] = s;
    __syncthreads();
    s = reds[0] + reds[1] + reds[2] + reds[3] + reds[4] + reds[5] + reds[6] + reds[7];

    const float inv = 1.0f / s;
    cnt = 0;
    for (int i = tid; i < NHW; i += 256) p[i] = v[cnt++] * inv;
}

// ---------------------------------------------------------------------------
// k_out: out[c][n] = cam[c][n] + alpha * sum_k cam[c][k]*attn[n][k].
// BM=128 (over CH), BN=64, TM=8, TN=8, 128 threads. Both operands K-fast.
// ---------------------------------------------------------------------------
__global__ __launch_bounds__(128) void k_out(const float* __restrict__ cam,
                                             const float* __restrict__ alpha_p,
                                             float* __restrict__ out) {
    __shared__ float As[BK][128 + 4];
    __shared__ float Bs[BK][64 + 4];

    const int b  = blockIdx.z;
    const int c0 = blockIdx.y * 128;
    const int n0 = blockIdx.x * 64;
    const float* camb = cam + (size_t)b * CH * NHW;
    const float* ab   = g_attn + (size_t)b * NHW * NHW;

    const int tid = threadIdx.x;
    const int ar = tid >> 2;          // 0..31
    const int ak = (tid & 3) << 2;
    const int tx = tid & 7;
    const int ty = tid >> 3;          // 0..15

    u64 acc[4][8] = {};

    for (int k0 = 0; k0 < NHW; k0 += BK) {
        #pragma unroll
        for (int r = 0; r < 4; ++r) {
            float4 av = *(const float4*)(camb + (size_t)(c0 + ar + 32 * r) * NHW + k0 + ak);
            As[ak + 0][ar + 32 * r] = av.x; As[ak + 1][ar + 32 * r] = av.y;
            As[ak + 2][ar + 32 * r] = av.z; As[ak + 3][ar + 32 * r] = av.w;
        }
        #pragma unroll
        for (int r = 0; r < 2; ++r) {
            float4 bv = *(const float4*)(ab + (size_t)(n0 + ar + 32 * r) * NHW + k0 + ak);
            Bs[ak + 0][ar + 32 * r] = bv.x; Bs[ak + 1][ar + 32 * r] = bv.y;
            Bs[ak + 2][ar + 32 * r] = bv.z; Bs[ak + 3][ar + 32 * r] = bv.w;
        }
        __syncthreads();

        #pragma unroll
        for (int k = 0; k < BK; ++k) {
            const ulonglong2* ap = (const ulonglong2*)&As[k][ty * 8];
            ulonglong2 alo = ap[0], ahi = ap[1];
            u64 av[4] = {alo.x, alo.y, ahi.x, ahi.y};
            float4 b0 = *(const float4*)&Bs[k][tx * 8];
            float4 b1 = *(const float4*)&Bs[k][tx * 8 + 4];
            u64 bb[8] = {pack2(b0.x, b0.x), pack2(b0.y, b0.y), pack2(b0.z, b0.z), pack2(b0.w, b0.w),
                         pack2(b1.x, b1.x), pack2(b1.y, b1.y), pack2(b1.z, b1.z), pack2(b1.w, b1.w)};
            #pragma unroll
            for (int p = 0; p < 4; ++p)
                #pragma unroll
                for (int j = 0; j < 8; ++j) ffma2(acc[p][j], av[p], bb[j]);
        }
        __syncthreads();
    }

    const float alpha = *alpha_p;
    float* ob = out + (size_t)b * CH * NHW;
    #pragma unroll
    for (int p = 0; p < 4; ++p) {
        const int row0 = c0 + ty * 8 + 2 * p;
        float2 c[8];
        #pragma unroll
        for (int j = 0; j < 8; ++j) c[j] = unpack2(acc[p][j]);
        size_t o0 = (size_t)row0 * NHW + n0 + tx * 8;
        size_t o1 = o0 + NHW;
        float4 cv;
        cv = *(const float4*)(camb + o0);
        *(float4*)(ob + o0) = make_float4(cv.x + alpha * c[0].x, cv.y + alpha * c[1].x,
                                          cv.z + alpha * c[2].x, cv.w + alpha * c[3].x);
        cv = *(const float4*)(camb + o0 + 4);
        *(float4*)(ob + o0 + 4) = make_float4(cv.x + alpha * c[4].x, cv.y + alpha * c[5].x,
                                              cv.z + alpha * c[6].x, cv.w + alpha * c[7].x);
        cv = *(const float4*)(camb + o1);
        *(float4*)(ob + o1) = make_float4(cv.x + alpha * c[0].y, cv.y + alpha * c[1].y,
                                          cv.z + alpha * c[2].y, cv.w + alpha * c[3].y);
        cv = *(const float4*)(camb + o1 + 4);
        *(float4*)(ob + o1 + 4) = make_float4(cv.x + alpha * c[4].y, cv.y + alpha * c[5].y,
                                              cv.z + alpha * c[6].y, cv.w + alpha * c[7].y);
    }
}

// ---------------------------------------------------------------------------
extern "C" void kernel_launch(void* const* d_in, const int* in_sizes, int n_in,
                              void* d_out, int out_size) {
    const float* cam   = (const float*)d_in[0];
    const float* feat  = (const float*)d_in[1];
    const float* W1    = (const float*)d_in[2];
    const float* W2    = (const float*)d_in[3];
    const float* alpha = (const float*)d_in[4];
    float* out = (float*)d_out;

    k_conv<<<dim3(NHW / 64, MID / 128, BATCH), 256>>>(feat, W1, W2);
    k_logits<<<dim3(NHW / 64, NHW / 64, BATCH), 64>>>();
    k_softmax<<<BATCH * NHW, 256>>>();
    k_out<<<dim3(NHW / 64, CH / 128, BATCH), 128>>>(cam, alpha, out);
}

// round 4
// speedup vs baseline: 2.0427x; 1.7734x over previous
#include <cuda_runtime.h>
#include <cuda_bf16.h>
#include <cstdint>

#define BATCH 32
#define CH    2048
#define NHW   576
#define MID   256
#define BK    16

typedef unsigned long long u64;
typedef uint32_t u32;

// ------------------------- scratch (device globals) -------------------------
__device__ float g_f1[(size_t)BATCH * MID * NHW];
__device__ float g_f2[(size_t)BATCH * MID * NHW];
__device__ float g_attn[(size_t)BATCH * NHW * NHW];
__device__ __nv_bfloat16 g_cam_h[(size_t)BATCH * CH * NHW];
__device__ __nv_bfloat16 g_cam_l[(size_t)BATCH * CH * NHW];
__device__ __nv_bfloat16 g_feat_h[(size_t)BATCH * CH * NHW];
__device__ __nv_bfloat16 g_feat_l[(size_t)BATCH * CH * NHW];
__device__ __nv_bfloat16 g_attn_h[(size_t)BATCH * NHW * NHW];
__device__ __nv_bfloat16 g_attn_l[(size_t)BATCH * NHW * NHW];
__device__ __nv_bfloat16 g_Wh[512 * 2048];   // rows 0-255: W1, 256-511: W2
__device__ __nv_bfloat16 g_Wl[512 * 2048];

// ------------------------- helpers -------------------------
__device__ __forceinline__ void ffma2(u64& c, u64 a, u64 b) {
    asm("fma.rn.f32x2 %0, %1, %2, %3;" : "=l"(c) : "l"(a), "l"(b), "l"(c));
}
__device__ __forceinline__ u64 pack2(float x, float y) {
    u64 r; asm("mov.b64 %0, {%1, %2};" : "=l"(r) : "f"(x), "f"(y)); return r;
}
__device__ __forceinline__ float2 unpack2(u64 v) {
    float2 r; asm("mov.b64 {%0, %1}, %2;" : "=f"(r.x), "=f"(r.y) : "l"(v)); return r;
}
__device__ __forceinline__ u32 smem_u32(const void* p) {
    u32 a;
    asm("{ .reg .u64 t; cvta.to.shared.u64 t, %1; cvt.u32.u64 %0, t; }" : "=r"(a) : "l"(p));
    return a;
}
__device__ __forceinline__ u64 gaddr(const void* p) {
    u64 a; asm("cvta.to.global.u64 %0, %1;" : "=l"(a) : "l"(p)); return a;
}
__device__ __forceinline__ void cp16(u32 s, u64 g) {
    asm volatile("cp.async.cg.shared.global [%0], [%1], 16;" :: "r"(s), "l"(g) : "memory");
}
#define CP_COMMIT() asm volatile("cp.async.commit_group;" ::: "memory")
#define CP_WAIT(n)  asm volatile("cp.async.wait_group %0;" :: "n"(n) : "memory")

__device__ __forceinline__ void ldm_x4(u32* r, u32 a) {
    asm volatile("ldmatrix.sync.aligned.m8n8.x4.shared.b16 {%0,%1,%2,%3}, [%4];"
        : "=r"(r[0]), "=r"(r[1]), "=r"(r[2]), "=r"(r[3]) : "r"(a));
}
__device__ __forceinline__ void ldm_x2(u32* r, u32 a) {
    asm volatile("ldmatrix.sync.aligned.m8n8.x2.shared.b16 {%0,%1}, [%2];"
        : "=r"(r[0]), "=r"(r[1]) : "r"(a));
}
__device__ __forceinline__ void ldm_x2t(u32* r, u32 a) {
    asm volatile("ldmatrix.sync.aligned.m8n8.x2.trans.shared.b16 {%0,%1}, [%2];"
        : "=r"(r[0]), "=r"(r[1]) : "r"(a));
}
__device__ __forceinline__ void mma_bf16(float* d, const u32* a, const u32* b) {
    asm volatile(
        "mma.sync.aligned.m16n8k16.row.col.f32.bf16.bf16.f32 "
        "{%0,%1,%2,%3}, {%4,%5,%6,%7}, {%8,%9}, {%0,%1,%2,%3};"
        : "+f"(d[0]), "+f"(d[1]), "+f"(d[2]), "+f"(d[3])
        : "r"(a[0]), "r"(a[1]), "r"(a[2]), "r"(a[3]), "r"(b[0]), "r"(b[1]));
}

extern __shared__ __align__(16) char dsm[];

// ---------------------------------------------------------------------------
// Converters: fp32 -> (hi, lo) bf16 pair.
// ---------------------------------------------------------------------------
__device__ __forceinline__ void split4(float4 v, __nv_bfloat16* h, __nv_bfloat16* l, size_t i) {
    __nv_bfloat16 h0 = __float2bfloat16_rn(v.x), h1 = __float2bfloat16_rn(v.y);
    __nv_bfloat16 h2 = __float2bfloat16_rn(v.z), h3 = __float2bfloat16_rn(v.w);
    __nv_bfloat16 l0 = __float2bfloat16_rn(v.x - __bfloat162float(h0));
    __nv_bfloat16 l1 = __float2bfloat16_rn(v.y - __bfloat162float(h1));
    __nv_bfloat16 l2 = __float2bfloat16_rn(v.z - __bfloat162float(h2));
    __nv_bfloat16 l3 = __float2bfloat16_rn(v.w - __bfloat162float(h3));
    *(__nv_bfloat162*)(h + i)     = __nv_bfloat162(h0, h1);
    *(__nv_bfloat162*)(h + i + 2) = __nv_bfloat162(h2, h3);
    *(__nv_bfloat162*)(l + i)     = __nv_bfloat162(l0, l1);
    *(__nv_bfloat162*)(l + i + 2) = __nv_bfloat162(l2, l3);
}

__global__ __launch_bounds__(256) void k_cvt_cam(const float* __restrict__ src) {
    size_t i = ((size_t)blockIdx.x * 256 + threadIdx.x) * 4;
    split4(*(const float4*)(src + i), g_cam_h, g_cam_l, i);
}
__global__ __launch_bounds__(256) void k_cvt_feat(const float* __restrict__ src) {
    size_t i = ((size_t)blockIdx.x * 256 + threadIdx.x) * 4;
    split4(*(const float4*)(src + i), g_feat_h, g_feat_l, i);
}
__global__ __launch_bounds__(256) void k_cvt_w(const float* __restrict__ W1,
                                               const float* __restrict__ W2) {
    size_t i = ((size_t)blockIdx.x * 256 + threadIdx.x) * 4;   // over 512*2048
    const float* src = (i < (size_t)256 * 2048) ? (W1 + i) : (W2 + i - (size_t)256 * 2048);
    split4(*(const float4*)src, g_Wh, g_Wl, i);
}

// ---------------------------------------------------------------------------
// k_conv_mma: [f1; f2] (512 x 576 per batch) = [W1;W2](512x2048) @ feat(2048x576)
// bf16 4-term split, mma.sync m16n8k16, fp32 accum, fp32 output.
// BM=128, BN=144, K-chunk 32, 2-stage cp.async pipeline.
// 8 warps: wm=wid&3 (32 rows each), wn=wid>>2 (72 cols each).
// smem stage: Ah[128x32]@80B rows (10240) | Al (10240) | Bh[32x144]@304B rows (9728) | Bl (9728)
// ---------------------------------------------------------------------------
#define KC_STAGE 39936

__global__ __launch_bounds__(256) void k_conv_mma() {
    const int tid = threadIdx.x, wid = tid >> 5, l = tid & 31;
    const int b = blockIdx.z, m0 = blockIdx.y * 128, n0 = blockIdx.x * 144;
    const int wm = wid & 3, wn = wid >> 2;
    const u32 smb = smem_u32(dsm);

    const u64 gWh = gaddr(g_Wh), gWl = gaddr(g_Wl);
    const u64 gFh = gaddr(g_feat_h), gFl = gaddr(g_feat_l);

    float acc[2][9][4] = {};

    auto load_tiles = [&](int k0, u32 st) {
        #pragma unroll
        for (int t = 0; t < 9; ++t) {
            const int idx = tid + 256 * t;
            if (idx < 2176) {
                if (idx < 1024) {
                    const int a = idx & 511, r = a >> 2, c = a & 3;
                    const u64 g = ((idx < 512) ? gWh : gWl) +
                        ((u64)(m0 + r) * 2048 + (u32)(k0 + c * 8)) * 2;
                    cp16(st + ((idx < 512) ? 0u : 10240u) + (u32)r * 80 + (u32)c * 16, g);
                } else {
                    const int a2 = idx - 1024;
                    const int half = a2 >= 576;
                    const int j = a2 - (half ? 576 : 0);
                    const int r = j / 18, c = j - r * 18;
                    const u64 g = (half ? gFl : gFh) +
                        ((u64)(b * CH + k0 + r) * NHW + (u32)(n0 + c * 8)) * 2;
                    cp16(st + 20480u + (half ? 9728u : 0u) + (u32)r * 304 + (u32)c * 16, g);
                }
            }
        }
    };

    load_tiles(0, smb);
    CP_COMMIT();

    // per-lane ldmatrix offsets
    const u32 a_base = (u32)(wm * 32 + (l & 7) + ((l >> 3) & 1) * 8) * 80 + ((l >> 4) & 1) * 16;
    const int lb = l & 15;
    const u32 b_base = (u32)(((lb >> 3) & 1) * 8 + (lb & 7)) * 304 + (u32)(wn * 72) * 2;

    for (int it = 0; it < 64; ++it) {
        const u32 st = smb + (u32)(it & 1) * KC_STAGE;
        if (it < 63) {
            load_tiles((it + 1) * 32, smb + (u32)((it + 1) & 1) * KC_STAGE);
            CP_COMMIT();
            CP_WAIT(1);
        } else {
            CP_WAIT(0);
        }
        __syncthreads();

        #pragma unroll
        for (int k16 = 0; k16 < 2; ++k16) {
            u32 ah[2][4], al[2][4];
            #pragma unroll
            for (int mb = 0; mb < 2; ++mb) {
                ldm_x4(ah[mb], st + a_base + (u32)mb * 1280 + (u32)k16 * 32);
                ldm_x4(al[mb], st + 10240u + a_base + (u32)mb * 1280 + (u32)k16 * 32);
            }
            #pragma unroll
            for (int nb = 0; nb < 9; ++nb) {
                u32 bh[2], bl[2];
                const u32 ba = st + 20480u + b_base + (u32)k16 * (16 * 304) + (u32)nb * 16;
                ldm_x2t(bh, ba);
                ldm_x2t(bl, ba + 9728u);
                #pragma unroll
                for (int mb = 0; mb < 2; ++mb) {
                    mma_bf16(acc[mb][nb], ah[mb], bh);
                    mma_bf16(acc[mb][nb], ah[mb], bl);
                    mma_bf16(acc[mb][nb], al[mb], bh);
                    mma_bf16(acc[mb][nb], al[mb], bl);
                }
            }
        }
        __syncthreads();
    }

    float* dst = (m0 < 256) ? g_f1 : g_f2;
    const int mrb = (m0 & 255) + wm * 32;
    const int g = l >> 2, t2 = (l & 3) * 2;
    #pragma unroll
    for (int mb = 0; mb < 2; ++mb) {
        #pragma unroll
        for (int nb = 0; nb < 9; ++nb) {
            const int row = mrb + mb * 16 + g;
            const int col = n0 + wn * 72 + nb * 8 + t2;
            const size_t o = ((size_t)b * MID + row) * NHW + col;
            *(float2*)(dst + o)            = make_float2(acc[mb][nb][0], acc[mb][nb][1]);
            *(float2*)(dst + o + 8 * NHW)  = make_float2(acc[mb][nb][2], acc[mb][nb][3]);
        }
    }
}

// ---------------------------------------------------------------------------
// k_logits (FFMA2, unchanged): logits = f1^T f2 per batch.
// ---------------------------------------------------------------------------
__global__ __launch_bounds__(64) void k_logits() {
    __shared__ float As[BK][64];
    __shared__ float Bs[BK][64];

    const int b  = blockIdx.z;
    const int i0 = blockIdx.y * 64;
    const int j0 = blockIdx.x * 64;
    const float* f1b = g_f1 + (size_t)b * MID * NHW;
    const float* f2b = g_f2 + (size_t)b * MID * NHW;

    const int tid = threadIdx.x;
    const int lc = (tid & 15) << 2;
    const int lk = tid >> 4;
    const int tx = tid & 7;
    const int ty = tid >> 3;

    u64 acc[4][8] = {};

    for (int k0 = 0; k0 < MID; k0 += BK) {
        #pragma unroll
        for (int r = 0; r < 4; ++r) {
            int kr = lk + 4 * r;
            *(float4*)&As[kr][lc] = *(const float4*)(f1b + (size_t)(k0 + kr) * NHW + i0 + lc);
            *(float4*)&Bs[kr][lc] = *(const float4*)(f2b + (size_t)(k0 + kr) * NHW + j0 + lc);
        }
        __syncthreads();

        #pragma unroll
        for (int k = 0; k < BK; ++k) {
            const ulonglong2* ap = (const ulonglong2*)&As[k][ty * 8];
            ulonglong2 alo = ap[0], ahi = ap[1];
            u64 av[4] = {alo.x, alo.y, ahi.x, ahi.y};
            float4 b0 = *(const float4*)&Bs[k][tx * 8];
            float4 b1 = *(const float4*)&Bs[k][tx * 8 + 4];
            u64 bb[8] = {pack2(b0.x, b0.x), pack2(b0.y, b0.y), pack2(b0.z, b0.z), pack2(b0.w, b0.w),
                         pack2(b1.x, b1.x), pack2(b1.y, b1.y), pack2(b1.z, b1.z), pack2(b1.w, b1.w)};
            #pragma unroll
            for (int p = 0; p < 4; ++p)
                #pragma unroll
                for (int j = 0; j < 8; ++j) ffma2(acc[p][j], av[p], bb[j]);
        }
        __syncthreads();
    }

    float* ab = g_attn + (size_t)b * NHW * NHW;
    #pragma unroll
    for (int p = 0; p < 4; ++p) {
        const int row0 = i0 + ty * 8 + 2 * p;
        float2 c[8];
        #pragma unroll
        for (int j = 0; j < 8; ++j) c[j] = unpack2(acc[p][j]);
        size_t o0 = (size_t)row0 * NHW + j0 + tx * 8;
        size_t o1 = o0 + NHW;
        *(float4*)(ab + o0)     = make_float4(c[0].x, c[1].x, c[2].x, c[3].x);
        *(float4*)(ab + o0 + 4) = make_float4(c[4].x, c[5].x, c[6].x, c[7].x);
        *(float4*)(ab + o1)     = make_float4(c[0].y, c[1].y, c[2].y, c[3].y);
        *(float4*)(ab + o1 + 4) = make_float4(c[4].y, c[5].y, c[6].y, c[7].y);
    }
}

// ---------------------------------------------------------------------------
// k_softmax: row softmax over fp32 logits; emits attn as bf16 (hi, lo).
// ---------------------------------------------------------------------------
__global__ __launch_bounds__(256) void k_softmax() {
    const size_t row = blockIdx.x;
    const float* p = g_attn + row * NHW;
    __nv_bfloat16* oh = g_attn_h + row * NHW;
    __nv_bfloat16* ol = g_attn_l + row * NHW;
    const int tid = threadIdx.x;

    float v[3];
    int cnt = 0;
    float m = -1e30f;
    for (int i = tid; i < NHW; i += 256) { v[cnt] = p[i]; m = fmaxf(m, v[cnt]); ++cnt; }
    #pragma unroll
    for (int o = 16; o > 0; o >>= 1) m = fmaxf(m, __shfl_xor_sync(0xffffffffu, m, o));
    __shared__ float redm[8], reds[8];
    if ((tid & 31) == 0) redm[tid >> 5] = m;
    __syncthreads();
    m = fmaxf(fmaxf(fmaxf(redm[0], redm[1]), fmaxf(redm[2], redm[3])),
              fmaxf(fmaxf(redm[4], redm[5]), fmaxf(redm[6], redm[7])));

    float s = 0.f;
    for (int c = 0; c < cnt; ++c) { v[c] = __expf(v[c] - m); s += v[c]; }
    #pragma unroll
    for (int o = 16; o > 0; o >>= 1) s += __shfl_xor_sync(0xffffffffu, s, o);
    if ((tid & 31) == 0) reds[tid >> 5] = s;
    __syncthreads();
    s = reds[0] + reds[1] + reds[2] + reds[3] + reds[4] + reds[5] + reds[6] + reds[7];

    const float inv = 1.0f / s;
    cnt = 0;
    for (int i = tid; i < NHW; i += 256) {
        float pv = v[cnt++] * inv;
        __nv_bfloat16 h = __float2bfloat16_rn(pv);
        __nv_bfloat16 lo = __float2bfloat16_rn(pv - __bfloat162float(h));
        oh[i] = h; ol[i] = lo;
    }
}

// ---------------------------------------------------------------------------
// k_out_mma: out[c][n] = cam[c][n] + alpha * sum_k cam[c][k]*attn[n][k]
// bf16 3-term split (camh*ah + camh*al + caml*ah). BM=128, BN=96, K-chunk 32.
// 8 warps: wm=wid&1 (64 rows), wn=wid>>1 (24 cols).
// smem stage: Ah[128x32]@80B (10240) | Al (10240) | Bh[96x32]@80B (7680) | Bl (7680)
// ---------------------------------------------------------------------------
#define KO_STAGE 35840

__global__ __launch_bounds__(256) void k_out_mma(const float* __restrict__ cam,
                                                 const float* __restrict__ alpha_p,
                                                 float* __restrict__ out) {
    const int tid = threadIdx.x, wid = tid >> 5, l = tid & 31;
    const int b = blockIdx.z, c0 = blockIdx.y * 128, n0 = blockIdx.x * 96;
    const int wm = wid & 1, wn = wid >> 1;
    const u32 smb = smem_u32(dsm);

    const u64 gCh = gaddr(g_cam_h), gCl = gaddr(g_cam_l);
    const u64 gAh = gaddr(g_attn_h), gAl = gaddr(g_attn_l);

    float acc[4][3][4] = {};

    auto load_tiles = [&](int k0, u32 st) {
        #pragma unroll
        for (int t = 0; t < 7; ++t) {
            const int idx = tid + 256 * t;   // 0..1791
            if (idx < 1024) {
                const int a = idx & 511, r = a >> 2, c = a & 3;
                const u64 g = ((idx < 512) ? gCh : gCl) +
                    ((u64)(b * CH + c0 + r) * NHW + (u32)(k0 + c * 8)) * 2;
                cp16(st + ((idx < 512) ? 0u : 10240u) + (u32)r * 80 + (u32)c * 16, g);
            } else {
                const int j = idx - 1024;
                const int half = j >= 384;
                const int j2 = j - (half ? 384 : 0);
                const int r = j2 >> 2, c = j2 & 3;
                const u64 g = (half ? gAl : gAh) +
                    ((u64)(b * NHW + n0 + r) * NHW + (u32)(k0 + c * 8)) * 2;
                cp16(st + 20480u + (half ? 7680u : 0u) + (u32)r * 80 + (u32)c * 16, g);
            }
        }
    };

    load_tiles(0, smb);
    CP_COMMIT();

    const u32 a_base = (u32)(wm * 64 + (l & 7) + ((l >> 3) & 1) * 8) * 80 + ((l >> 4) & 1) * 16;
    const int lb = l & 15;
    const u32 b_base = (u32)(wn * 24 + (lb & 7)) * 80 + (u32)((lb >> 3) & 1) * 16;

    for (int it = 0; it < 18; ++it) {
        const u32 st = smb + (u32)(it & 1) * KO_STAGE;
        if (it < 17) {
            load_tiles((it + 1) * 32, smb + (u32)((it + 1) & 1) * KO_STAGE);
            CP_COMMIT();
            CP_WAIT(1);
        } else {
            CP_WAIT(0);
        }
        __syncthreads();

        #pragma unroll
        for (int k16 = 0; k16 < 2; ++k16) {
            u32 ah[4][4], al[4][4];
            #pragma unroll
            for (int mb = 0; mb < 4; ++mb) {
                ldm_x4(ah[mb], st + a_base + (u32)mb * 1280 + (u32)k16 * 32);
                ldm_x4(al[mb], st + 10240u + a_base + (u32)mb * 1280 + (u32)k16 * 32);
            }
            #pragma unroll
            for (int nb = 0; nb < 3; ++nb) {
                u32 bh[2], bl[2];
                const u32 ba = st + 20480u + b_base + (u32)nb * 640 + (u32)k16 * 32;
                ldm_x2(bh, ba);
                ldm_x2(bl, ba + 7680u);
                #pragma unroll
                for (int mb = 0; mb < 4; ++mb) {
                    mma_bf16(acc[mb][nb], ah[mb], bh);
                    mma_bf16(acc[mb][nb], ah[mb], bl);
                    mma_bf16(acc[mb][nb], al[mb], bh);
                }
            }
        }
        __syncthreads();
    }

    const float alpha = *alpha_p;
    const int g = l >> 2, t2 = (l & 3) * 2;
    #pragma unroll
    for (int mb = 0; mb < 4; ++mb) {
        #pragma unroll
        for (int nb = 0; nb < 3; ++nb) {
            const int row = c0 + wm * 64 + mb * 16 + g;
            const int col = n0 + wn * 24 + nb * 8 + t2;
            const size_t o = ((size_t)b * CH + row) * NHW + col;
            float2 cv0 = *(const float2*)(cam + o);
            float2 cv1 = *(const float2*)(cam + o + 8 * NHW);
            *(float2*)(out + o) = make_float2(cv0.x + alpha * acc[mb][nb][0],
                                              cv0.y + alpha * acc[mb][nb][1]);
            *(float2*)(out + o + 8 * NHW) = make_float2(cv1.x + alpha * acc[mb][nb][2],
                                                        cv1.y + alpha * acc[mb][nb][3]);
        }
    }
}

// ---------------------------------------------------------------------------
extern "C" void kernel_launch(void* const* d_in, const int* in_sizes, int n_in,
                              void* d_out, int out_size) {
    const float* cam   = (const float*)d_in[0];
    const float* feat  = (const float*)d_in[1];
    const float* W1    = (const float*)d_in[2];
    const float* W2    = (const float*)d_in[3];
    const float* alpha = (const float*)d_in[4];
    float* out = (float*)d_out;

    cudaFuncSetAttribute(k_conv_mma, cudaFuncAttributeMaxDynamicSharedMemorySize, 2 * KC_STAGE);
    cudaFuncSetAttribute(k_out_mma,  cudaFuncAttributeMaxDynamicSharedMemorySize, 2 * KO_STAGE);

    k_cvt_cam<<<36864, 256>>>(cam);
    k_cvt_feat<<<36864, 256>>>(feat);
    k_cvt_w<<<1024, 256>>>(W1, W2);
    k_conv_mma<<<dim3(4, 4, 32), 256, 2 * KC_STAGE>>>();
    k_logits<<<dim3(9, 9, 32), 64>>>();
    k_softmax<<<BATCH * NHW, 256>>>();
    k_out_mma<<<dim3(6, 16, 32), 256, 2 * KO_STAGE>>>(cam, alpha, out);
}

// round 6
// speedup vs baseline: 2.3532x; 1.1520x over previous
#include <cuda_runtime.h>
#include <cuda_bf16.h>
#include <cstdint>

#define BATCH 32
#define CH    2048
#define NHW   576
#define MID   256

typedef unsigned long long u64;
typedef uint32_t u32;

// ------------------------- scratch (device globals) -------------------------
__device__ float g_attn[(size_t)BATCH * NHW * NHW];
__device__ __nv_bfloat16 g_cam_h[(size_t)BATCH * CH * NHW];
__device__ __nv_bfloat16 g_cam_l[(size_t)BATCH * CH * NHW];
__device__ __nv_bfloat16 g_feat_h[(size_t)BATCH * CH * NHW];
__device__ __nv_bfloat16 g_feat_l[(size_t)BATCH * CH * NHW];
__device__ __nv_bfloat16 g_attn_h[(size_t)BATCH * NHW * NHW];
__device__ __nv_bfloat16 g_attn_l[(size_t)BATCH * NHW * NHW];
__device__ __nv_bfloat16 g_Wh[512 * 2048];   // rows 0-255: W1, 256-511: W2
__device__ __nv_bfloat16 g_Wl[512 * 2048];
// f1/f2 transposed split-bf16: [b][n][m], m contiguous (MID=256)
__device__ __nv_bfloat16 g_f1t_h[(size_t)BATCH * NHW * MID];
__device__ __nv_bfloat16 g_f1t_l[(size_t)BATCH * NHW * MID];
__device__ __nv_bfloat16 g_f2t_h[(size_t)BATCH * NHW * MID];
__device__ __nv_bfloat16 g_f2t_l[(size_t)BATCH * NHW * MID];

// ------------------------- helpers -------------------------
__device__ __forceinline__ u32 smem_u32(const void* p) {
    u32 a;
    asm("{ .reg .u64 t; cvta.to.shared.u64 t, %1; cvt.u32.u64 %0, t; }" : "=r"(a) : "l"(p));
    return a;
}
__device__ __forceinline__ u64 gaddr(const void* p) {
    u64 a; asm("cvta.to.global.u64 %0, %1;" : "=l"(a) : "l"(p)); return a;
}
__device__ __forceinline__ void cp16(u32 s, u64 g) {
    asm volatile("cp.async.cg.shared.global [%0], [%1], 16;" :: "r"(s), "l"(g) : "memory");
}
#define CP_COMMIT() asm volatile("cp.async.commit_group;" ::: "memory")
#define CP_WAIT(n)  asm volatile("cp.async.wait_group %0;" :: "n"(n) : "memory")

__device__ __forceinline__ void ldm_x4(u32* r, u32 a) {
    asm volatile("ldmatrix.sync.aligned.m8n8.x4.shared.b16 {%0,%1,%2,%3}, [%4];"
        : "=r"(r[0]), "=r"(r[1]), "=r"(r[2]), "=r"(r[3]) : "r"(a));
}
__device__ __forceinline__ void ldm_x2(u32* r, u32 a) {
    asm volatile("ldmatrix.sync.aligned.m8n8.x2.shared.b16 {%0,%1}, [%2];"
        : "=r"(r[0]), "=r"(r[1]) : "r"(a));
}
__device__ __forceinline__ void ldm_x2t(u32* r, u32 a) {
    asm volatile("ldmatrix.sync.aligned.m8n8.x2.trans.shared.b16 {%0,%1}, [%2];"
        : "=r"(r[0]), "=r"(r[1]) : "r"(a));
}
__device__ __forceinline__ void mma_bf16(float* d, const u32* a, const u32* b) {
    asm volatile(
        "mma.sync.aligned.m16n8k16.row.col.f32.bf16.bf16.f32 "
        "{%0,%1,%2,%3}, {%4,%5,%6,%7}, {%8,%9}, {%0,%1,%2,%3};"
        : "+f"(d[0]), "+f"(d[1]), "+f"(d[2]), "+f"(d[3])
        : "r"(a[0]), "r"(a[1]), "r"(a[2]), "r"(a[3]), "r"(b[0]), "r"(b[1]));
}

extern __shared__ __align__(16) char dsm[];

// ---------------------------------------------------------------------------
// Converters: fp32 -> (hi, lo) bf16 pair.
// ---------------------------------------------------------------------------
__device__ __forceinline__ void split4(float4 v, __nv_bfloat16* h, __nv_bfloat16* l, size_t i) {
    __nv_bfloat16 h0 = __float2bfloat16_rn(v.x), h1 = __float2bfloat16_rn(v.y);
    __nv_bfloat16 h2 = __float2bfloat16_rn(v.z), h3 = __float2bfloat16_rn(v.w);
    __nv_bfloat16 l0 = __float2bfloat16_rn(v.x - __bfloat162float(h0));
    __nv_bfloat16 l1 = __float2bfloat16_rn(v.y - __bfloat162float(h1));
    __nv_bfloat16 l2 = __float2bfloat16_rn(v.z - __bfloat162float(h2));
    __nv_bfloat16 l3 = __float2bfloat16_rn(v.w - __bfloat162float(h3));
    *(__nv_bfloat162*)(h + i)     = __nv_bfloat162(h0, h1);
    *(__nv_bfloat162*)(h + i + 2) = __nv_bfloat162(h2, h3);
    *(__nv_bfloat162*)(l + i)     = __nv_bfloat162(l0, l1);
    *(__nv_bfloat162*)(l + i + 2) = __nv_bfloat162(l2, l3);
}

__global__ __launch_bounds__(256) void k_cvt_cam(const float* __restrict__ src) {
    size_t i = ((size_t)blockIdx.x * 256 + threadIdx.x) * 4;
    split4(*(const float4*)(src + i), g_cam_h, g_cam_l, i);
}
__global__ __launch_bounds__(256) void k_cvt_feat(const float* __restrict__ src) {
    size_t i = ((size_t)blockIdx.x * 256 + threadIdx.x) * 4;
    split4(*(const float4*)(src + i), g_feat_h, g_feat_l, i);
}
__global__ __launch_bounds__(256) void k_cvt_w(const float* __restrict__ W1,
                                               const float* __restrict__ W2) {
    size_t i = ((size_t)blockIdx.x * 256 + threadIdx.x) * 4;   // over 512*2048
    const float* src = (i < (size_t)256 * 2048) ? (W1 + i) : (W2 + i - (size_t)256 * 2048);
    split4(*(const float4*)src, g_Wh, g_Wl, i);
}

// ---------------------------------------------------------------------------
// k_conv_mma: [f1; f2] (512 x 576 per batch) = [W1;W2](512x2048) @ feat(2048x576)
// bf16 3-term split (WhFh + WhFl + WlFh), mma.sync, fp32 accum.
// Output: TRANSPOSED split-bf16 f1t/f2t[n][m] via smem transpose.
// BM=128, BN=144, K-chunk 32, 2-stage cp.async pipeline, 8 warps.
// ---------------------------------------------------------------------------
#define KC_STAGE 39936

__global__ __launch_bounds__(256) void k_conv_mma() {
    const int tid = threadIdx.x, wid = tid >> 5, l = tid & 31;
    const int b = blockIdx.z, m0 = blockIdx.y * 128, n0 = blockIdx.x * 144;
    const int wm = wid & 3, wn = wid >> 2;
    const u32 smb = smem_u32(dsm);

    const u64 gWh = gaddr(g_Wh), gWl = gaddr(g_Wl);
    const u64 gFh = gaddr(g_feat_h), gFl = gaddr(g_feat_l);

    float acc[2][9][4] = {};

    auto load_tiles = [&](int k0, u32 st) {
        #pragma unroll
        for (int t = 0; t < 9; ++t) {
            const int idx = tid + 256 * t;
            if (idx < 2176) {
                if (idx < 1024) {
                    const int a = idx & 511, r = a >> 2, c = a & 3;
                    const u64 g = ((idx < 512) ? gWh : gWl) +
                        ((u64)(m0 + r) * 2048 + (u32)(k0 + c * 8)) * 2;
                    cp16(st + ((idx < 512) ? 0u : 10240u) + (u32)r * 80 + (u32)c * 16, g);
                } else {
                    const int a2 = idx - 1024;
                    const int half = a2 >= 576;
                    const int j = a2 - (half ? 576 : 0);
                    const int r = j / 18, c = j - r * 18;
                    const u64 g = (half ? gFl : gFh) +
                        ((u64)(b * CH + k0 + r) * NHW + (u32)(n0 + c * 8)) * 2;
                    cp16(st + 20480u + (half ? 9728u : 0u) + (u32)r * 304 + (u32)c * 16, g);
                }
            }
        }
    };

    load_tiles(0, smb);
    CP_COMMIT();

    const u32 a_base = (u32)(wm * 32 + (l & 7) + ((l >> 3) & 1) * 8) * 80 + ((l >> 4) & 1) * 16;
    const int lb = l & 15;
    const u32 b_base = (u32)(((lb >> 3) & 1) * 8 + (lb & 7)) * 304 + (u32)(wn * 72) * 2;

    for (int it = 0; it < 64; ++it) {
        const u32 st = smb + (u32)(it & 1) * KC_STAGE;
        if (it < 63) {
            load_tiles((it + 1) * 32, smb + (u32)((it + 1) & 1) * KC_STAGE);
            CP_COMMIT();
            CP_WAIT(1);
        } else {
            CP_WAIT(0);
        }
        __syncthreads();

        #pragma unroll
        for (int k16 = 0; k16 < 2; ++k16) {
            u32 ah[2][4], al[2][4];
            #pragma unroll
            for (int mb = 0; mb < 2; ++mb) {
                ldm_x4(ah[mb], st + a_base + (u32)mb * 1280 + (u32)k16 * 32);
                ldm_x4(al[mb], st + 10240u + a_base + (u32)mb * 1280 + (u32)k16 * 32);
            }
            #pragma unroll
            for (int nb = 0; nb < 9; ++nb) {
                u32 bh[2], bl[2];
                const u32 ba = st + 20480u + b_base + (u32)k16 * (16 * 304) + (u32)nb * 16;
                ldm_x2t(bh, ba);
                ldm_x2t(bl, ba + 9728u);
                #pragma unroll
                for (int mb = 0; mb < 2; ++mb) {
                    mma_bf16(acc[mb][nb], ah[mb], bh);
                    mma_bf16(acc[mb][nb], ah[mb], bl);
                    mma_bf16(acc[mb][nb], al[mb], bh);
                }
            }
        }
        __syncthreads();
    }

    // --- epilogue: smem transpose -> split bf16, write f{1,2}t[n][m] ---
    // Th: [144 rows n][128 cols m] bf16 (256B row) at dsm+0; Tl at dsm+36864.
    const int g = l >> 2, t2 = (l & 3) * 2;
    #pragma unroll
    for (int mb = 0; mb < 2; ++mb) {
        #pragma unroll
        for (int nb = 0; nb < 9; ++nb) {
            const int ml = wm * 32 + mb * 16 + g;
            const int nl = wn * 72 + nb * 8 + t2;
            #pragma unroll
            for (int q = 0; q < 4; ++q) {
                const float v = acc[mb][nb][q];
                const int m_ = ml + (q >> 1) * 8;
                const int n_ = nl + (q & 1);
                __nv_bfloat16 h = __float2bfloat16_rn(v);
                __nv_bfloat16 lo = __float2bfloat16_rn(v - __bfloat162float(h));
                *(__nv_bfloat16*)(dsm + (u32)n_ * 256 + (u32)m_ * 2) = h;
                *(__nv_bfloat16*)(dsm + 36864u + (u32)n_ * 256 + (u32)m_ * 2) = lo;
            }
        }
    }
    __syncthreads();

    __nv_bfloat16* dh = (m0 < 256) ? g_f1t_h : g_f2t_h;
    __nv_bfloat16* dl = (m0 < 256) ? g_f1t_l : g_f2t_l;
    const int cb0 = m0 & 255;   // 0 or 128 within the 256-wide m dim
    #pragma unroll
    for (int t = 0; t < 9; ++t) {
        const int idx = tid + 256 * t;   // 0..2303
        const int j = idx >> 4, c = idx & 15;
        const size_t off = ((size_t)b * NHW + n0 + j) * MID + cb0 + c * 8;
        *(uint4*)(dh + off) = *(const uint4*)(dsm + (u32)j * 256 + (u32)c * 16);
        *(uint4*)(dl + off) = *(const uint4*)(dsm + 36864u + (u32)j * 256 + (u32)c * 16);
    }
}

// ---------------------------------------------------------------------------
// k_logits_mma: logits[i][j] = sum_m f1t[i][m]*f2t[j][m]. K=256, 3-term split.
// BM=BN=96, K-chunk 32, 8 warps (wm: 2x48 rows, wn: 4x24 cols), 2-stage pipe.
// smem stage: Ah 96x32@80B (7680) | Al (7680) | Bh (7680) | Bl (7680)
// ---------------------------------------------------------------------------
#define KL_STAGE 30720

__global__ __launch_bounds__(256) void k_logits_mma() {
    const int tid = threadIdx.x, wid = tid >> 5, l = tid & 31;
    const int b = blockIdx.z, i0 = blockIdx.y * 96, j0 = blockIdx.x * 96;
    const int wm = wid & 1, wn = wid >> 1;
    const u32 smb = smem_u32(dsm);

    const u64 g1h = gaddr(g_f1t_h), g1l = gaddr(g_f1t_l);
    const u64 g2h = gaddr(g_f2t_h), g2l = gaddr(g_f2t_l);

    float acc[3][3][4] = {};

    auto load_tiles = [&](int k0, u32 st) {
        #pragma unroll
        for (int t = 0; t < 6; ++t) {
            const int idx = tid + 256 * t;   // 0..1535
            const int side = idx >= 768;
            const int i2 = idx - (side ? 768 : 0);
            const int half = i2 >= 384;
            const int j2 = i2 - (half ? 384 : 0);
            const int r = j2 >> 2, c = j2 & 3;
            const u64 src = (side ? (half ? g2l : g2h) : (half ? g1l : g1h)) +
                ((u64)(b * NHW + (side ? j0 : i0) + r) * MID + (u32)(k0 + c * 8)) * 2;
            cp16(st + (side ? 15360u : 0u) + (half ? 7680u : 0u) + (u32)r * 80 + (u32)c * 16, src);
        }
    };

    load_tiles(0, smb);
    CP_COMMIT();

    const u32 a_base = (u32)(wm * 48 + (l & 7) + ((l >> 3) & 1) * 8) * 80 + ((l >> 4) & 1) * 16;
    const int lb = l & 15;
    const u32 b_base = (u32)(wn * 24 + (lb & 7)) * 80 + (u32)((lb >> 3) & 1) * 16;

    for (int it = 0; it < 8; ++it) {
        const u32 st = smb + (u32)(it & 1) * KL_STAGE;
        if (it < 7) {
            load_tiles((it + 1) * 32, smb + (u32)((it + 1) & 1) * KL_STAGE);
            CP_COMMIT();
            CP_WAIT(1);
        } else {
            CP_WAIT(0);
        }
        __syncthreads();

        #pragma unroll
        for (int k16 = 0; k16 < 2; ++k16) {
            u32 ah[3][4], al[3][4];
            #pragma unroll
            for (int mb = 0; mb < 3; ++mb) {
                ldm_x4(ah[mb], st + a_base + (u32)mb * 1280 + (u32)k16 * 32);
                ldm_x4(al[mb], st + 7680u + a_base + (u32)mb * 1280 + (u32)k16 * 32);
            }
            #pragma unroll
            for (int nb = 0; nb < 3; ++nb) {
                u32 bh[2], bl[2];
                const u32 ba = st + 15360u + b_base + (u32)nb * 640 + (u32)k16 * 32;
                ldm_x2(bh, ba);
                ldm_x2(bl, ba + 7680u);
                #pragma unroll
                for (int mb = 0; mb < 3; ++mb) {
                    mma_bf16(acc[mb][nb], ah[mb], bh);
                    mma_bf16(acc[mb][nb], ah[mb], bl);
                    mma_bf16(acc[mb][nb], al[mb], bh);
                }
            }
        }
        __syncthreads();
    }

    float* ab = g_attn + (size_t)b * NHW * NHW;
    const int g = l >> 2, t2 = (l & 3) * 2;
    #pragma unroll
    for (int mb = 0; mb < 3; ++mb) {
        #pragma unroll
        for (int nb = 0; nb < 3; ++nb) {
            const int row = i0 + wm * 48 + mb * 16 + g;
            const int col = j0 + wn * 24 + nb * 8 + t2;
            const size_t o = (size_t)row * NHW + col;
            *(float2*)(ab + o)           = make_float2(acc[mb][nb][0], acc[mb][nb][1]);
            *(float2*)(ab + o + 8 * NHW) = make_float2(acc[mb][nb][2], acc[mb][nb][3]);
        }
    }
}

// ---------------------------------------------------------------------------
// k_softmax: row softmax over fp32 logits; emits attn as bf16 (hi, lo).
// ---------------------------------------------------------------------------
__global__ __launch_bounds__(256) void k_softmax() {
    const size_t row = blockIdx.x;
    const float* p = g_attn + row * NHW;
    __nv_bfloat16* oh = g_attn_h + row * NHW;
    __nv_bfloat16* ol = g_attn_l + row * NHW;
    const int tid = threadIdx.x;

    float v[3];
    int cnt = 0;
    float m = -1e30f;
    for (int i = tid; i < NHW; i += 256) { v[cnt] = p[i]; m = fmaxf(m, v[cnt]); ++cnt; }
    #pragma unroll
    for (int o = 16; o > 0; o >>= 1) m = fmaxf(m, __shfl_xor_sync(0xffffffffu, m, o));
    __shared__ float redm[8], reds[8];
    if ((tid & 31) == 0) redm[tid >> 5] = m;
    __syncthreads();
    m = fmaxf(fmaxf(fmaxf(redm[0], redm[1]), fmaxf(redm[2], redm[3])),
              fmaxf(fmaxf(redm[4], redm[5]), fmaxf(redm[6], redm[7])));

    float s = 0.f;
    for (int c = 0; c < cnt; ++c) { v[c] = __expf(v[c] - m); s += v[c]; }
    #pragma unroll
    for (int o = 16; o > 0; o >>= 1) s += __shfl_xor_sync(0xffffffffu, s, o);
    if ((tid & 31) == 0) reds[tid >> 5] = s;
    __syncthreads();
    s = reds[0] + reds[1] + reds[2] + reds[3] + reds[4] + reds[5] + reds[6] + reds[7];

    const float inv = 1.0f / s;
    cnt = 0;
    for (int i = tid; i < NHW; i += 256) {
        float pv = v[cnt++] * inv;
        __nv_bfloat16 h = __float2bfloat16_rn(pv);
        __nv_bfloat16 lo = __float2bfloat16_rn(pv - __bfloat162float(h));
        oh[i] = h; ol[i] = lo;
    }
}

// ---------------------------------------------------------------------------
// k_out_mma: out[c][n] = cam[c][n] + alpha * sum_k cam[c][k]*attn[n][k]
// bf16 3-term split. BM=128, BN=96, K-chunk 32, 2-stage pipe, 8 warps.
// ---------------------------------------------------------------------------
#define KO_STAGE 35840

__global__ __launch_bounds__(256) void k_out_mma(const float* __restrict__ cam,
                                                 const float* __restrict__ alpha_p,
                                                 float* __restrict__ out) {
    const int tid = threadIdx.x, wid = tid >> 5, l = tid & 31;
    const int b = blockIdx.z, c0 = blockIdx.y * 128, n0 = blockIdx.x * 96;
    const int wm = wid & 1, wn = wid >> 1;
    const u32 smb = smem_u32(dsm);

    const u64 gCh = gaddr(g_cam_h), gCl = gaddr(g_cam_l);
    const u64 gAh = gaddr(g_attn_h), gAl = gaddr(g_attn_l);

    float acc[4][3][4] = {};

    auto load_tiles = [&](int k0, u32 st) {
        #pragma unroll
        for (int t = 0; t < 7; ++t) {
            const int idx = tid + 256 * t;   // 0..1791
            if (idx < 1024) {
                const int a = idx & 511, r = a >> 2, c = a & 3;
                const u64 g = ((idx < 512) ? gCh : gCl) +
                    ((u64)(b * CH + c0 + r) * NHW + (u32)(k0 + c * 8)) * 2;
                cp16(st + ((idx < 512) ? 0u : 10240u) + (u32)r * 80 + (u32)c * 16, g);
            } else {
                const int j = idx - 1024;
                const int half = j >= 384;
                const int j2 = j - (half ? 384 : 0);
                const int r = j2 >> 2, c = j2 & 3;
                const u64 g = (half ? gAl : gAh) +
                    ((u64)(b * NHW + n0 + r) * NHW + (u32)(k0 + c * 8)) * 2;
                cp16(st + 20480u + (half ? 7680u : 0u) + (u32)r * 80 + (u32)c * 16, g);
            }
        }
    };

    load_tiles(0, smb);
    CP_COMMIT();

    const u32 a_base = (u32)(wm * 64 + (l & 7) + ((l >> 3) & 1) * 8) * 80 + ((l >> 4) & 1) * 16;
    const int lb = l & 15;
    const u32 b_base = (u32)(wn * 24 + (lb & 7)) * 80 + (u32)((lb >> 3) & 1) * 16;

    for (int it = 0; it < 18; ++it) {
        const u32 st = smb + (u32)(it & 1) * KO_STAGE;
        if (it < 17) {
            load_tiles((it + 1) * 32, smb + (u32)((it + 1) & 1) * KO_STAGE);
            CP_COMMIT();
            CP_WAIT(1);
        } else {
            CP_WAIT(0);
        }
        __syncthreads();

        #pragma unroll
        for (int k16 = 0; k16 < 2; ++k16) {
            u32 ah[4][4], al[4][4];
            #pragma unroll
            for (int mb = 0; mb < 4; ++mb) {
                ldm_x4(ah[mb], st + a_base + (u32)mb * 1280 + (u32)k16 * 32);
                ldm_x4(al[mb], st + 10240u + a_base + (u32)mb * 1280 + (u32)k16 * 32);
            }
            #pragma unroll
            for (int nb = 0; nb < 3; ++nb) {
                u32 bh[2], bl[2];
                const u32 ba = st + 20480u + b_base + (u32)nb * 640 + (u32)k16 * 32;
                ldm_x2(bh, ba);
                ldm_x2(bl, ba + 7680u);
                #pragma unroll
                for (int mb = 0; mb < 4; ++mb) {
                    mma_bf16(acc[mb][nb], ah[mb], bh);
                    mma_bf16(acc[mb][nb], ah[mb], bl);
                    mma_bf16(acc[mb][nb], al[mb], bh);
                }
            }
        }
        __syncthreads();
    }

    const float alpha = *alpha_p;
    const int g = l >> 2, t2 = (l & 3) * 2;
    #pragma unroll
    for (int mb = 0; mb < 4; ++mb) {
        #pragma unroll
        for (int nb = 0; nb < 3; ++nb) {
            const int row = c0 + wm * 64 + mb * 16 + g;
            const int col = n0 + wn * 24 + nb * 8 + t2;
            const size_t o = ((size_t)b * CH + row) * NHW + col;
            float2 cv0 = *(const float2*)(cam + o);
            float2 cv1 = *(const float2*)(cam + o + 8 * NHW);
            *(float2*)(out + o) = make_float2(cv0.x + alpha * acc[mb][nb][0],
                                              cv0.y + alpha * acc[mb][nb][1]);
            *(float2*)(out + o + 8 * NHW) = make_float2(cv1.x + alpha * acc[mb][nb][2],
                                                        cv1.y + alpha * acc[mb][nb][3]);
        }
    }
}

// ---------------------------------------------------------------------------
extern "C" void kernel_launch(void* const* d_in, const int* in_sizes, int n_in,
                              void* d_out, int out_size) {
    const float* cam   = (const float*)d_in[0];
    const float* feat  = (const float*)d_in[1];
    const float* W1    = (const float*)d_in[2];
    const float* W2    = (const float*)d_in[3];
    const float* alpha = (const float*)d_in[4];
    float* out = (float*)d_out;

    cudaFuncSetAttribute(k_conv_mma,   cudaFuncAttributeMaxDynamicSharedMemorySize, 2 * KC_STAGE);
    cudaFuncSetAttribute(k_logits_mma, cudaFuncAttributeMaxDynamicSharedMemorySize, 2 * KL_STAGE);
    cudaFuncSetAttribute(k_out_mma,    cudaFuncAttributeMaxDynamicSharedMemorySize, 2 * KO_STAGE);

    k_cvt_cam<<<36864, 256>>>(cam);
    k_cvt_feat<<<36864, 256>>>(feat);
    k_cvt_w<<<1024, 256>>>(W1, W2);
    k_conv_mma<<<dim3(4, 4, 32), 256, 2 * KC_STAGE>>>();
    k_logits_mma<<<dim3(6, 6, 32), 256, 2 * KL_STAGE>>>();
    k_softmax<<<BATCH * NHW, 256>>>();
    k_out_mma<<<dim3(6, 16, 32), 256, 2 * KO_STAGE>>>(cam, alpha, out);
}